// round 9
// baseline (speedup 1.0000x reference)
#include <cuda_runtime.h>
#include <cstdint>

typedef unsigned long long ull;
#define FULL 0xFFFFFFFFu

constexpr int NUM_GROUP  = 512;
constexpr int GROUP_SIZE = 32;
constexpr int TPB        = 512;
constexpr int MAXB       = 64;

__device__ int g_prog[MAXB];

__global__ void init_prog() {
    if (threadIdx.x < MAXB) g_prog[threadIdx.x] = 0;
}

// ---- packed f32x2 helpers (sm_100+) ----
__device__ __forceinline__ ull pack2(float a, float b) {
    ull r; asm("mov.b64 %0,{%1,%2};" : "=l"(r) : "f"(a), "f"(b)); return r;
}
__device__ __forceinline__ void unpack2(ull v, float& a, float& b) {
    asm("mov.b64 {%0,%1},%2;" : "=f"(a), "=f"(b) : "l"(v));
}
__device__ __forceinline__ ull addx2(ull a, ull b) {
    ull r; asm("add.rn.f32x2 %0,%1,%2;" : "=l"(r) : "l"(a), "l"(b)); return r;
}
__device__ __forceinline__ ull mulx2(ull a, ull b) {
    ull r; asm("mul.rn.f32x2 %0,%1,%2;" : "=l"(r) : "l"(a), "l"(b)); return r;
}
__device__ __forceinline__ ull fma2_(ull a, ull b, ull c) {
    ull r; asm("fma.rn.f32x2 %0,%1,%2,%3;" : "=l"(r) : "l"(a), "l"(b), "l"(c)); return r;
}
__device__ __forceinline__ uint32_t redux_max_u32(uint32_t v) {
    uint32_t r; asm("redux.sync.max.u32 %0, %1, 0xffffffff;" : "=r"(r) : "r"(v)); return r;
}
__device__ __forceinline__ uint32_t redux_min_u32(uint32_t v) {
    uint32_t r; asm("redux.sync.min.u32 %0, %1, 0xffffffff;" : "=r"(r) : "r"(v)); return r;
}
__device__ __forceinline__ void st_release_gpu(int* p, int v) {
    asm volatile("st.release.gpu.global.s32 [%0], %1;" :: "l"(p), "r"(v) : "memory");
}
__device__ __forceinline__ int ld_acquire_gpu(const int* p) {
    int v; asm volatile("ld.acquire.gpu.global.s32 %0, [%1];" : "=r"(v) : "l"(p) : "memory");
    return v;
}

// ============================================================
// Fused kernel, TPB=512:
//   blocks [0, B)        : FPS, one per batch (exclusive SM)
//   blocks [B, B + 32*B) : kNN, 16 groups per block, batch-major order
// ============================================================
__global__ __launch_bounds__(TPB)
void fused_kernel(const float* __restrict__ xyz,
                  float* __restrict__ nb,
                  float* __restrict__ centers,
                  int N, int B) {
    extern __shared__ float s[];
    float* sx = s;
    float* sy = s + N;
    float* sz = s + 2 * N;

    const int tid  = threadIdx.x;
    const int lane = tid & 31;
    const int warp = tid >> 5;

    if (blockIdx.x < (unsigned)B) {
        // ==================== FPS: 16 points per thread ====================
        const int b = blockIdx.x;
        const float* X = xyz + (size_t)b * 3 * N;
        const float* Y = X + N;
        const float* Z = Y + N;

        __shared__ uint32_t vbuf[2][32];   // per-warp value table (lanes 16..31 stay 0)
        __shared__ uint32_t idslot[2];     // rare multi-warp-tie resolution
        __shared__ float    pktc[2][3];    // [parity][cx,cy,cz] published by winner
        if (tid < 64) vbuf[tid >> 5][tid & 31] = 0u;
        if (tid < 2)  idslot[tid] = 0xFFFFFFFFu;

        // 8 packed pairs per thread (N <= 8192); no smem staging needed for FPS
        ull  pxp[8], pyp[8], pzp[8];
        float md[16];
        const int NP = (N + 2 * TPB - 1) / (2 * TPB);
        #pragma unroll
        for (int i = 0; i < 8; i++) {
            if (i < NP) {
                int n0 = 2 * (tid + i * TPB);
                bool v = (n0 + 1 < N);
                float x0 = v ? X[n0] : 0.f, x1 = v ? X[n0 + 1] : 0.f;
                float y0 = v ? Y[n0] : 0.f, y1 = v ? Y[n0 + 1] : 0.f;
                float z0 = v ? Z[n0] : 0.f, z1 = v ? Z[n0 + 1] : 0.f;
                pxp[i] = pack2(x0, x1);
                pyp[i] = pack2(y0, y1);
                pzp[i] = pack2(z0, z1);
                md[2 * i]     = v ? 1e10f : -1.0f;
                md[2 * i + 1] = v ? 1e10f : -1.0f;
            }
        }

        float cx = X[0], cy = Y[0], cz = Z[0];
        float* cout = centers + (size_t)b * NUM_GROUP * 3;
        __syncthreads();

        for (int it = 0; it < NUM_GROUP; it++) {
            const int p = it & 1;
            if (tid == 0) {
                cout[it * 3 + 0] = cx;
                cout[it * 3 + 1] = cy;
                cout[it * 3 + 2] = cz;
                if ((it & 7) == 7) st_release_gpu(&g_prog[b], it - 7);   // lagged publish
            }
            if (it == NUM_GROUP - 1) break;    // last center stored; no selection needed

            const ull ncx = pack2(-cx, -cx), ncy = pack2(-cy, -cy), ncz = pack2(-cz, -cz);

            // lean hot loop: value-only tracking
            float bm0 = -2.0f, bm1 = -2.0f;
            #pragma unroll
            for (int i = 0; i < 8; i++) {
                if (i < NP) {
                    ull dx = addx2(pxp[i], ncx);
                    ull dy = addx2(pyp[i], ncy);
                    ull dz = addx2(pzp[i], ncz);
                    ull m  = mulx2(dx, dx);
                    m = fma2_(dy, dy, m);
                    m = fma2_(dz, dz, m);      // == fmaf(dz,dz,fmaf(dy,dy,dx*dx)) per lane
                    float d0, d1; unpack2(m, d0, d1);
                    float m0 = fminf(md[2 * i],     d0);
                    float m1 = fminf(md[2 * i + 1], d1);
                    md[2 * i]     = m0;
                    md[2 * i + 1] = m1;
                    bm0 = fmaxf(bm0, m0);
                    bm1 = fmaxf(bm1, m1);
                }
            }
            float bv = fmaxf(bm0, bm1);

            uint32_t fb   = (bv >= 0.0f) ? __float_as_uint(bv) : 0u;
            uint32_t wmax = redux_max_u32(fb);
            if (lane == 0) vbuf[p][warp] = wmax;
            __syncthreads();                            // bar A

            if (tid == TPB - 1) idslot[p ^ 1] = 0xFFFFFFFFu;   // reset for it+1 tie path

            uint32_t v2 = vbuf[p][lane];
            uint32_t m2 = redux_max_u32(v2);            // block max (same in all warps)
            unsigned tiemask = __ballot_sync(FULL, v2 == m2) & 0xFFFFu;
            const bool unique = (__popc(tiemask) == 1);

            uint32_t q = 0xFFFFFFFFu;                   // orig-id candidate (tie path scope)
            if (unique) {
                // fast path: unique winner warp resolves coords from registers
                if (warp == (__ffs(tiemask) - 1)) {
                    uint32_t msk = 0u;
                    #pragma unroll
                    for (int j = 0; j < 16; j++)
                        msk |= ((j >> 1) < NP && md[j] == bv) ? (1u << j) : 0u;
                    uint32_t qq = 0xFFFFFFFFu;
                    int j = 0;
                    if (fb == m2 && msk) {
                        j  = __ffs(msk) - 1;             // id monotone in j -> smallest id
                        qq = (uint32_t)(2 * (tid + (j >> 1) * TPB) + (j & 1));
                    }
                    uint32_t idmin = redux_min_u32(qq);
                    if (qq == idmin) {
                        float a0, a1, b0, b1, c0, c1;
                        unpack2(pxp[j >> 1], a0, a1);
                        unpack2(pyp[j >> 1], b0, b1);
                        unpack2(pzp[j >> 1], c0, c1);
                        pktc[p][0] = (j & 1) ? a1 : a0;
                        pktc[p][1] = (j & 1) ? b1 : b0;
                        pktc[p][2] = (j & 1) ? c1 : c0;
                    }
                }
            } else {
                // rare exact-tie across warps (block-uniform branch)
                if (wmax == m2) {
                    uint32_t msk = 0u;
                    #pragma unroll
                    for (int j = 0; j < 16; j++)
                        msk |= ((j >> 1) < NP && md[j] == bv) ? (1u << j) : 0u;
                    if (fb == m2 && msk) {
                        int j = __ffs(msk) - 1;
                        q = (uint32_t)(2 * (tid + (j >> 1) * TPB) + (j & 1));
                    }
                    uint32_t idw = redux_min_u32(q);
                    if (lane == 0) atomicMin(&idslot[p], idw);
                }
            }
            __syncthreads();                            // bar B (drains winner STS)

            if (!unique) {                               // block-uniform
                if (q != 0xFFFFFFFFu && q == idslot[p]) {
                    uint32_t msk = 0u;
                    #pragma unroll
                    for (int j = 0; j < 16; j++)
                        msk |= ((j >> 1) < NP && md[j] == bv) ? (1u << j) : 0u;
                    int j = __ffs(msk) - 1;
                    float a0, a1, b0, b1, c0, c1;
                    unpack2(pxp[j >> 1], a0, a1);
                    unpack2(pyp[j >> 1], b0, b1);
                    unpack2(pzp[j >> 1], c0, c1);
                    pktc[p][0] = (j & 1) ? a1 : a0;
                    pktc[p][1] = (j & 1) ? b1 : b0;
                    pktc[p][2] = (j & 1) ? c1 : c0;
                }
                __syncthreads();                        // bar C (rare)
            }

            cx = pktc[p][0];                            // one parallel smem read
            cy = pktc[p][1];
            cz = pktc[p][2];
        }
        if (tid == 0) st_release_gpu(&g_prog[b], NUM_GROUP);
    } else {
        // ==================== kNN top-32 (batch-major block order) ====================
        const int kb    = blockIdx.x - B;
        const int b     = kb % B;
        const int chunk = kb / B;
        const int g     = chunk * 16 + warp;

        const float* X = xyz + (size_t)b * 3 * N;
        const float4* X4 = (const float4*)X;
        float4* sx4 = (float4*)sx;
        float4* sy4 = (float4*)sy;
        float4* sz4 = (float4*)sz;
        const int N4 = N >> 2;
        for (int n = tid; n < N4; n += TPB) {
            sx4[n] = X4[n];
            sy4[n] = X4[N4 + n];
            sz4[n] = X4[2 * N4 + n];
        }
        __syncthreads();

        while (ld_acquire_gpu(&g_prog[b]) < g + 1) __nanosleep(128);

        const float* c = centers + ((size_t)b * NUM_GROUP + g) * 3;
        const float cx = __ldcg(&c[0]), cy = __ldcg(&c[1]), cz = __ldcg(&c[2]);

        // init with first 32 points, bitonic sort ascending u64 keys
        ull key;
        {
            float dx = sx[lane] - cx, dy = sy[lane] - cy, dz = sz[lane] - cz;
            float d2 = fmaf(dz, dz, fmaf(dy, dy, dx * dx));
            key = ((ull)__float_as_uint(d2) << 32) | (uint32_t)lane;
        }
        #pragma unroll
        for (int k2 = 2; k2 <= 32; k2 <<= 1) {
            #pragma unroll
            for (int j = k2 >> 1; j > 0; j >>= 1) {
                ull partner = __shfl_xor_sync(FULL, key, j);
                bool lower  = (lane & j) == 0;
                bool asc    = (lane & k2) == 0;
                ull mn = (key < partner) ? key : partner;
                ull mx = (key < partner) ? partner : key;
                key = (lower == asc) ? mn : mx;
            }
        }
        ull kmax = __shfl_sync(FULL, key, 31);

        // scalar step for points [32, 64)
        {
            int idx = 32 + lane;
            float dx = sx[idx] - cx, dy = sy[idx] - cy, dz = sz[idx] - cz;
            float d2 = fmaf(dz, dz, fmaf(dy, dy, dx * dx));
            ull nk = ((ull)__float_as_uint(d2) << 32) | (uint32_t)idx;
            unsigned mask = __ballot_sync(FULL, nk < kmax);
            while (mask) {
                int src = __ffs(mask) - 1;
                mask &= mask - 1;
                ull cand = __shfl_sync(FULL, nk, src);
                if (cand >= kmax) continue;
                int pos = __popc(__ballot_sync(FULL, key < cand));
                ull up  = __shfl_up_sync(FULL, key, 1);
                if (lane == pos)      key = cand;
                else if (lane > pos)  key = up;
                kmax = __shfl_sync(FULL, key, 31);
            }
        }

        // packed stream: 64 candidates per step
        const float2* sx2 = (const float2*)sx;
        const float2* sy2 = (const float2*)sy;
        const float2* sz2 = (const float2*)sz;
        const ull ncx = pack2(-cx, -cx), ncy = pack2(-cy, -cy), ncz = pack2(-cz, -cz);

        for (int base = 64; base < N; base += 64) {
            int h = (base >> 1) + lane;
            float2 xx = sx2[h], yy = sy2[h], zz = sz2[h];
            ull dx = addx2(pack2(xx.x, xx.y), ncx);
            ull dy = addx2(pack2(yy.x, yy.y), ncy);
            ull dz = addx2(pack2(zz.x, zz.y), ncz);
            ull m  = mulx2(dx, dx);
            m = fma2_(dy, dy, m);
            m = fma2_(dz, dz, m);
            float d0, d1; unpack2(m, d0, d1);
            int i0 = base + 2 * lane;
            ull k0 = ((ull)__float_as_uint(d0) << 32) | (uint32_t)i0;
            ull k1 = ((ull)__float_as_uint(d1) << 32) | (uint32_t)(i0 + 1);

            unsigned m0 = __ballot_sync(FULL, k0 < kmax);
            unsigned m1 = __ballot_sync(FULL, k1 < kmax);
            while (m0) {
                int src = __ffs(m0) - 1;
                m0 &= m0 - 1;
                ull cand = __shfl_sync(FULL, k0, src);
                if (cand >= kmax) continue;
                int pos = __popc(__ballot_sync(FULL, key < cand));
                ull up  = __shfl_up_sync(FULL, key, 1);
                if (lane == pos)      key = cand;
                else if (lane > pos)  key = up;
                kmax = __shfl_sync(FULL, key, 31);
            }
            while (m1) {
                int src = __ffs(m1) - 1;
                m1 &= m1 - 1;
                ull cand = __shfl_sync(FULL, k1, src);
                if (cand >= kmax) continue;
                int pos = __popc(__ballot_sync(FULL, key < cand));
                ull up  = __shfl_up_sync(FULL, key, 1);
                if (lane == pos)      key = cand;
                else if (lane > pos)  key = up;
                kmax = __shfl_sync(FULL, key, 31);
            }
        }

        // emit: neighborhood = point - center (lane-sorted ascending = top_k order)
        int idx = (int)(uint32_t)key;
        float ox = sx[idx] - cx, oy = sy[idx] - cy, oz = sz[idx] - cz;
        size_t o = (((size_t)b * NUM_GROUP + g) * GROUP_SIZE + lane) * 3;
        nb[o + 0] = ox;
        nb[o + 1] = oy;
        nb[o + 2] = oz;
    }
}

// ============================================================
extern "C" void kernel_launch(void* const* d_in, const int* in_sizes, int n_in,
                              void* d_out, int out_size) {
    const float* xyz = (const float*)d_in[0];
    float* out = (float*)d_out;

    const int B = out_size / (NUM_GROUP * (GROUP_SIZE + 1) * 3);
    const int N = in_sizes[0] / (3 * B);

    float* nb      = out;
    float* centers = out + (size_t)B * NUM_GROUP * GROUP_SIZE * 3;

    const int knnBlocks = B * (NUM_GROUP / 16);
    size_t smem = (size_t)3 * N * sizeof(float);
    if (smem < 120 * 1024) smem = 120 * 1024;   // force 1 block/SM

    init_prog<<<1, MAXB>>>();

    cudaFuncSetAttribute(fused_kernel, cudaFuncAttributeMaxDynamicSharedMemorySize, (int)smem);
    fused_kernel<<<B + knnBlocks, TPB, smem>>>(xyz, nb, centers, N, B);
}

// round 10
// speedup vs baseline: 1.3719x; 1.3719x over previous
#include <cuda_runtime.h>
#include <cstdint>

typedef unsigned long long ull;
#define FULL 0xFFFFFFFFu

constexpr int NUM_GROUP  = 512;
constexpr int GROUP_SIZE = 32;
constexpr int TPB        = 512;
constexpr int MAXB       = 64;

__device__ int g_prog[MAXB];

__global__ void init_prog() {
    if (threadIdx.x < MAXB) g_prog[threadIdx.x] = 0;
}

// ---- packed f32x2 helpers (sm_100+) ----
__device__ __forceinline__ ull pack2(float a, float b) {
    ull r; asm("mov.b64 %0,{%1,%2};" : "=l"(r) : "f"(a), "f"(b)); return r;
}
__device__ __forceinline__ void unpack2(ull v, float& a, float& b) {
    asm("mov.b64 {%0,%1},%2;" : "=f"(a), "=f"(b) : "l"(v));
}
__device__ __forceinline__ ull addx2(ull a, ull b) {
    ull r; asm("add.rn.f32x2 %0,%1,%2;" : "=l"(r) : "l"(a), "l"(b)); return r;
}
__device__ __forceinline__ ull mulx2(ull a, ull b) {
    ull r; asm("mul.rn.f32x2 %0,%1,%2;" : "=l"(r) : "l"(a), "l"(b)); return r;
}
__device__ __forceinline__ ull fma2_(ull a, ull b, ull c) {
    ull r; asm("fma.rn.f32x2 %0,%1,%2,%3;" : "=l"(r) : "l"(a), "l"(b), "l"(c)); return r;
}
__device__ __forceinline__ uint32_t redux_max_u32(uint32_t v) {
    uint32_t r; asm("redux.sync.max.u32 %0, %1, 0xffffffff;" : "=r"(r) : "r"(v)); return r;
}
__device__ __forceinline__ uint32_t redux_min_u32(uint32_t v) {
    uint32_t r; asm("redux.sync.min.u32 %0, %1, 0xffffffff;" : "=r"(r) : "r"(v)); return r;
}
__device__ __forceinline__ void st_release_gpu(int* p, int v) {
    asm volatile("st.release.gpu.global.s32 [%0], %1;" :: "l"(p), "r"(v) : "memory");
}
__device__ __forceinline__ int ld_acquire_gpu(const int* p) {
    int v; asm volatile("ld.acquire.gpu.global.s32 %0, [%1];" : "=r"(v) : "l"(p) : "memory");
    return v;
}

// ============================================================
// FPS body, specialized on pairs-per-thread NP (compile-time).
// ============================================================
template <int NPc>
__device__ __forceinline__ void fps_body(
    const float* __restrict__ X, const float* __restrict__ Y, const float* __restrict__ Z,
    float* __restrict__ sx, float* __restrict__ sy, float* __restrict__ sz,
    float* __restrict__ cout, int* progp, int N,
    int tid, int lane, int warp)
{
    __shared__ uint32_t vbuf[2][32];     // per-warp value table (lanes 16..31 stay 0)
    __shared__ uint32_t idslot[2];       // winner's original id, double buffered
    if (tid < 64) vbuf[tid >> 5][tid & 31] = 0u;
    if (tid < 2)  idslot[tid] = 0xFFFFFFFFu;

    ull  pxp[NPc], pyp[NPc], pzp[NPc];
    float md[2 * NPc];
    float2* sx2w = (float2*)sx;
    float2* sy2w = (float2*)sy;
    float2* sz2w = (float2*)sz;
    #pragma unroll
    for (int i = 0; i < NPc; i++) {
        int p  = tid + i * TPB;
        int n0 = 2 * p;
        bool v = (n0 + 1 < N);
        float x0 = v ? X[n0] : 0.f, x1 = v ? X[n0 + 1] : 0.f;
        float y0 = v ? Y[n0] : 0.f, y1 = v ? Y[n0 + 1] : 0.f;
        float z0 = v ? Z[n0] : 0.f, z1 = v ? Z[n0 + 1] : 0.f;
        pxp[i] = pack2(x0, x1);
        pyp[i] = pack2(y0, y1);
        pzp[i] = pack2(z0, z1);
        md[2 * i]     = v ? 1e10f : -1.0f;
        md[2 * i + 1] = v ? 1e10f : -1.0f;
        if (v) {
            sx2w[p] = make_float2(x0, x1);   // staged for coord fetch after selection
            sy2w[p] = make_float2(y0, y1);
            sz2w[p] = make_float2(z0, z1);
        }
    }

    float cx = X[0], cy = Y[0], cz = Z[0];
    __syncthreads();

    for (int it = 0; it < NUM_GROUP; it++) {
        const int p = it & 1;
        if (tid == 0) {
            cout[it * 3 + 0] = cx;
            cout[it * 3 + 1] = cy;
            cout[it * 3 + 2] = cz;
            if ((it & 7) == 7) st_release_gpu(progp, it - 7);   // lagged publish
        }
        const ull ncx = pack2(-cx, -cx), ncy = pack2(-cy, -cy), ncz = pack2(-cz, -cz);

        // lean hot loop: value-only tracking (fully unrolled, no guards)
        float bm0 = -2.0f, bm1 = -2.0f;
        #pragma unroll
        for (int i = 0; i < NPc; i++) {
            ull dx = addx2(pxp[i], ncx);
            ull dy = addx2(pyp[i], ncy);
            ull dz = addx2(pzp[i], ncz);
            ull m  = mulx2(dx, dx);
            m = fma2_(dy, dy, m);
            m = fma2_(dz, dz, m);          // == fmaf(dz,dz,fmaf(dy,dy,dx*dx)) per lane
            float d0, d1; unpack2(m, d0, d1);
            float m0 = fminf(md[2 * i],     d0);
            float m1 = fminf(md[2 * i + 1], d1);
            md[2 * i]     = m0;
            md[2 * i + 1] = m1;
            bm0 = fmaxf(bm0, m0);
            bm1 = fmaxf(bm1, m1);
        }
        float bv = fmaxf(bm0, bm1);

        // publish warp VALUE only (nonneg distances -> float bits monotone)
        uint32_t fb   = (bv >= 0.0f) ? __float_as_uint(bv) : 0u;
        uint32_t wmax = redux_max_u32(fb);
        if (lane == 0) vbuf[p][warp] = wmax;
        __syncthreads();                           // bar A

        // block max from the 16-entry table (all warps, cheap)
        uint32_t v2 = vbuf[p][lane];
        uint32_t m2 = redux_max_u32(v2);
        unsigned tiemask = __ballot_sync(FULL, v2 == m2) & 0xFFFFu;

        // reset the OTHER idslot for iteration it+1 (its last read was pre-barA)
        if (tid == TPB - 1) idslot[p ^ 1] = 0xFFFFFFFFu;

        // ONLY winning warp(s) resolve the index (warp-uniform branch).
        // Static mask rescan: 16 independent compares, no dynamic reg indexing.
        if (wmax == m2) {
            uint32_t q = 0xFFFFFFFFu;
            if (fb == m2) {
                uint32_t msk = 0u;
                #pragma unroll
                for (int j = 0; j < 2 * NPc; j++)
                    msk |= (md[j] == bv) ? (1u << j) : 0u;
                if (msk) {
                    int j = __ffs(msk) - 1;        // id monotone in j -> smallest id
                    q = (uint32_t)(2 * (tid + (j >> 1) * TPB) + (j & 1));
                }
            }
            uint32_t idmin = redux_min_u32(q);
            if (lane == 0) {
                if (__popc(tiemask) == 1) idslot[p] = idmin;             // sole winner
                else                      atomicMin(&idslot[p], idmin);  // exact tie
            }
        }
        __syncthreads();                           // bar B

        int idx = (int)idslot[p];
        cx = sx[idx]; cy = sy[idx]; cz = sz[idx];  // broadcast LDS
    }
    if (tid == 0) st_release_gpu(progp, NUM_GROUP);
}

// ============================================================
// Fused kernel, TPB=512:
//   blocks [0, B)        : FPS, one per batch (exclusive SM)
//   blocks [B, B + 32*B) : kNN, 16 groups per block, batch-major order
// ============================================================
__global__ __launch_bounds__(TPB)
void fused_kernel(const float* __restrict__ xyz,
                  float* __restrict__ nb,
                  float* __restrict__ centers,
                  int N, int B) {
    extern __shared__ float s[];
    float* sx = s;
    float* sy = s + N;
    float* sz = s + 2 * N;

    const int tid  = threadIdx.x;
    const int lane = tid & 31;
    const int warp = tid >> 5;

    if (blockIdx.x < (unsigned)B) {
        // ==================== FPS ====================
        const int b = blockIdx.x;
        const float* X = xyz + (size_t)b * 3 * N;
        const float* Y = X + N;
        const float* Z = Y + N;
        float* cout = centers + (size_t)b * NUM_GROUP * 3;

        if (N == 8192) {
            fps_body<8>(X, Y, Z, sx, sy, sz, cout, &g_prog[b], N, tid, lane, warp);
        } else {
            fps_body<8>(X, Y, Z, sx, sy, sz, cout, &g_prog[b], N, tid, lane, warp);
        }
    } else {
        // ==================== kNN top-32 (batch-major block order) ====================
        const int kb    = blockIdx.x - B;
        const int b     = kb % B;                   // batch-major: wave-1 = early groups
        const int chunk = kb / B;
        const int g     = chunk * 16 + warp;        // this warp's group

        const float* X = xyz + (size_t)b * 3 * N;
        const float4* X4 = (const float4*)X;
        float4* sx4 = (float4*)sx;
        float4* sy4 = (float4*)sy;
        float4* sz4 = (float4*)sz;
        const int N4 = N >> 2;
        for (int n = tid; n < N4; n += TPB) {
            sx4[n] = X4[n];
            sy4[n] = X4[N4 + n];
            sz4[n] = X4[2 * N4 + n];
        }
        __syncthreads();

        // lane0-only poll (32x less L2 traffic against FPS's writes)
        if (lane == 0) {
            while (ld_acquire_gpu(&g_prog[b]) < g + 1) __nanosleep(512);
        }
        __syncwarp();

        const float* c = centers + ((size_t)b * NUM_GROUP + g) * 3;
        const float cx = __ldcg(&c[0]), cy = __ldcg(&c[1]), cz = __ldcg(&c[2]);

        // init with first 32 points, bitonic sort ascending u64 keys
        ull key;
        {
            float dx = sx[lane] - cx, dy = sy[lane] - cy, dz = sz[lane] - cz;
            float d2 = fmaf(dz, dz, fmaf(dy, dy, dx * dx));
            key = ((ull)__float_as_uint(d2) << 32) | (uint32_t)lane;
        }
        #pragma unroll
        for (int k2 = 2; k2 <= 32; k2 <<= 1) {
            #pragma unroll
            for (int j = k2 >> 1; j > 0; j >>= 1) {
                ull partner = __shfl_xor_sync(FULL, key, j);
                bool lower  = (lane & j) == 0;
                bool asc    = (lane & k2) == 0;
                ull mn = (key < partner) ? key : partner;
                ull mx = (key < partner) ? partner : key;
                key = (lower == asc) ? mn : mx;
            }
        }
        ull kmax = __shfl_sync(FULL, key, 31);

        // scalar step for points [32, 64)
        {
            int idx = 32 + lane;
            float dx = sx[idx] - cx, dy = sy[idx] - cy, dz = sz[idx] - cz;
            float d2 = fmaf(dz, dz, fmaf(dy, dy, dx * dx));
            ull nk = ((ull)__float_as_uint(d2) << 32) | (uint32_t)idx;
            unsigned mask = __ballot_sync(FULL, nk < kmax);
            while (mask) {
                int src = __ffs(mask) - 1;
                mask &= mask - 1;
                ull cand = __shfl_sync(FULL, nk, src);
                if (cand >= kmax) continue;
                int pos = __popc(__ballot_sync(FULL, key < cand));
                ull up  = __shfl_up_sync(FULL, key, 1);
                if (lane == pos)      key = cand;
                else if (lane > pos)  key = up;
                kmax = __shfl_sync(FULL, key, 31);
            }
        }

        // packed stream: 64 candidates per step
        const float2* sx2 = (const float2*)sx;
        const float2* sy2 = (const float2*)sy;
        const float2* sz2 = (const float2*)sz;
        const ull ncx = pack2(-cx, -cx), ncy = pack2(-cy, -cy), ncz = pack2(-cz, -cz);

        for (int base = 64; base < N; base += 64) {
            int h = (base >> 1) + lane;
            float2 xx = sx2[h], yy = sy2[h], zz = sz2[h];
            ull dx = addx2(pack2(xx.x, xx.y), ncx);
            ull dy = addx2(pack2(yy.x, yy.y), ncy);
            ull dz = addx2(pack2(zz.x, zz.y), ncz);
            ull m  = mulx2(dx, dx);
            m = fma2_(dy, dy, m);
            m = fma2_(dz, dz, m);
            float d0, d1; unpack2(m, d0, d1);
            int i0 = base + 2 * lane;
            ull k0 = ((ull)__float_as_uint(d0) << 32) | (uint32_t)i0;
            ull k1 = ((ull)__float_as_uint(d1) << 32) | (uint32_t)(i0 + 1);

            unsigned m0 = __ballot_sync(FULL, k0 < kmax);
            unsigned m1 = __ballot_sync(FULL, k1 < kmax);
            while (m0) {
                int src = __ffs(m0) - 1;
                m0 &= m0 - 1;
                ull cand = __shfl_sync(FULL, k0, src);
                if (cand >= kmax) continue;
                int pos = __popc(__ballot_sync(FULL, key < cand));
                ull up  = __shfl_up_sync(FULL, key, 1);
                if (lane == pos)      key = cand;
                else if (lane > pos)  key = up;
                kmax = __shfl_sync(FULL, key, 31);
            }
            while (m1) {
                int src = __ffs(m1) - 1;
                m1 &= m1 - 1;
                ull cand = __shfl_sync(FULL, k1, src);
                if (cand >= kmax) continue;
                int pos = __popc(__ballot_sync(FULL, key < cand));
                ull up  = __shfl_up_sync(FULL, key, 1);
                if (lane == pos)      key = cand;
                else if (lane > pos)  key = up;
                kmax = __shfl_sync(FULL, key, 31);
            }
        }

        // emit: neighborhood = point - center (lane-sorted ascending = top_k order)
        int idx = (int)(uint32_t)key;
        float ox = sx[idx] - cx, oy = sy[idx] - cy, oz = sz[idx] - cz;
        size_t o = (((size_t)b * NUM_GROUP + g) * GROUP_SIZE + lane) * 3;
        nb[o + 0] = ox;
        nb[o + 1] = oy;
        nb[o + 2] = oz;
    }
}

// ============================================================
extern "C" void kernel_launch(void* const* d_in, const int* in_sizes, int n_in,
                              void* d_out, int out_size) {
    const float* xyz = (const float*)d_in[0];
    float* out = (float*)d_out;

    const int B = out_size / (NUM_GROUP * (GROUP_SIZE + 1) * 3);
    const int N = in_sizes[0] / (3 * B);

    float* nb      = out;
    float* centers = out + (size_t)B * NUM_GROUP * GROUP_SIZE * 3;

    const int knnBlocks = B * (NUM_GROUP / 16);
    size_t smem = (size_t)3 * N * sizeof(float);
    if (smem < 120 * 1024) smem = 120 * 1024;   // force 1 block/SM

    init_prog<<<1, MAXB>>>();

    cudaFuncSetAttribute(fused_kernel, cudaFuncAttributeMaxDynamicSharedMemorySize, (int)smem);
    fused_kernel<<<B + knnBlocks, TPB, smem>>>(xyz, nb, centers, N, B);
}